// round 1
// baseline (speedup 1.0000x reference)
#include <cuda_runtime.h>
#include <cuda_bf16.h>

// Problem: 1M independent tasks, each a 40-step rollout of a tiny control
// system with two small MLPs, reduced to one scalar:
//   out = mean(err + eff) + alpha * mean(nor)
//
// Kernel 1: one thread per task, full rollout in registers, block-level
//           partial sums written to __device__ globals (deterministic).
// Kernel 2: single block reduces partials in double precision.

#define DT        0.05f
#define NSTEPS    40          // N_STEPS - 1 loop iterations
#define TPB       256
#define MAX_BLOCKS 8192

__device__ float g_part_err[MAX_BLOCKS];   // sum of (err + eff) per block
__device__ float g_part_nor[MAX_BLOCKS];   // sum of nor per block

// Accurate tanh: tanh(x) = sign(x) * (1 - 2/(exp(2|x|)+1))
// __expf -> MUFU.EX2 (+1 FMA), __fdividef -> MUFU.RCP (+mul). ~1e-6 rel err,
// numerically stable for all x (large |x| -> exp overflows to inf -> 1).
__device__ __forceinline__ float tanh_acc(float x) {
    float ax = fabsf(x);
    float e  = __expf(2.0f * ax);
    float r  = __fdividef(2.0f, e + 1.0f);
    float t  = 1.0f - r;
    return copysignf(t, x);
}

__global__ void __launch_bounds__(TPB)
rollout_kernel(const float* __restrict__ omega,
               const float* __restrict__ Wh1, const float* __restrict__ bh1,
               const float* __restrict__ Wh2, const float* __restrict__ bh2,
               const float* __restrict__ Wr1, const float* __restrict__ br1,
               const float* __restrict__ Wr2, const float* __restrict__ br2,
               int N)
{
    const int i = blockIdx.x * TPB + threadIdx.x;

    // --- Load shared tiny weights into registers (broadcast L1 hits) ---
    float wh1[16], vbh1[4], wh2[4], vbh2;
    float wr1[9],  vbr1[3], wr2[3], vbr2;
#pragma unroll
    for (int k = 0; k < 16; k++) wh1[k] = __ldg(Wh1 + k);
#pragma unroll
    for (int k = 0; k < 4;  k++) vbh1[k] = __ldg(bh1 + k);
#pragma unroll
    for (int k = 0; k < 4;  k++) wh2[k] = __ldg(Wh2 + k);
    vbh2 = __ldg(bh2);
#pragma unroll
    for (int k = 0; k < 9;  k++) wr1[k] = __ldg(Wr1 + k);
#pragma unroll
    for (int k = 0; k < 3;  k++) vbr1[k] = __ldg(br1 + k);
#pragma unroll
    for (int k = 0; k < 3;  k++) wr2[k] = __ldg(Wr2 + k);
    vbr2 = __ldg(br2);

    // --- Per-task target (s_star) ---
    float t0 = 0.0f, t1 = 0.0f;
    if (i < N) {
        t0 = __ldg(omega + i);       // omega[0, i]
        t1 = __ldg(omega + N + i);   // omega[1, i]
    }

    float s0 = 0.0f, s1 = 0.0f;
    float err = 0.0f, eff = 0.0f, nor = 0.0f;

#pragma unroll 2
    for (int st = 0; st < NSTEPS; st++) {
        float e0 = t0 - s0;
        float e1 = t1 - s1;
        err = fmaf(10.0f * e0, e0, err);
        err = fmaf(e1, e1, err);
        float zt = fmaf(0.1f, e1, e0);

        // human MLP: xh = [t0, t1, s0, s1]
        float h0 = tanh_acc(fmaf(wh1[0],  t0, fmaf(wh1[1],  t1, fmaf(wh1[2],  s0, fmaf(wh1[3],  s1, vbh1[0])))));
        float h1 = tanh_acc(fmaf(wh1[4],  t0, fmaf(wh1[5],  t1, fmaf(wh1[6],  s0, fmaf(wh1[7],  s1, vbh1[1])))));
        float h2 = tanh_acc(fmaf(wh1[8],  t0, fmaf(wh1[9],  t1, fmaf(wh1[10], s0, fmaf(wh1[11], s1, vbh1[2])))));
        float h3 = tanh_acc(fmaf(wh1[12], t0, fmaf(wh1[13], t1, fmaf(wh1[14], s0, fmaf(wh1[15], s1, vbh1[3])))));
        float z  = tanh_acc(fmaf(wh2[0], h0, fmaf(wh2[1], h1, fmaf(wh2[2], h2, fmaf(wh2[3], h3, vbh2)))));

        // robot MLP: xr = [s0, s1, z]
        float r0 = tanh_acc(fmaf(wr1[0], s0, fmaf(wr1[1], s1, fmaf(wr1[2], z, vbr1[0]))));
        float r1 = tanh_acc(fmaf(wr1[3], s0, fmaf(wr1[4], s1, fmaf(wr1[5], z, vbr1[1]))));
        float r2 = tanh_acc(fmaf(wr1[6], s0, fmaf(wr1[7], s1, fmaf(wr1[8], z, vbr1[2]))));
        float a  = fmaf(wr2[0], r0, fmaf(wr2[1], r1, fmaf(wr2[2], r2, vbr2)));

        // dynamics: s = A s + B a, A = [[1, dt],[0,1]], B = [0, dt]
        float ns0 = fmaf(DT, s1, s0);
        float ns1 = fmaf(DT, a,  s1);
        s0 = ns0; s1 = ns1;

        eff += (fabsf(z) > 0.01f) ? 1.0f : 0.0f;
        float d = zt - z;
        nor = fmaf(d, d, nor);
    }

    // final error term
    {
        float e0 = t0 - s0;
        float e1 = t1 - s1;
        err = fmaf(10.0f * e0, e0, err);
        err = fmaf(e1, e1, err);
    }

    float sumA = err + eff;   // contributes to expected_cost
    float sumB = nor;         // contributes to expected_diverg
    if (i >= N) { sumA = 0.0f; sumB = 0.0f; }

    // --- warp reduce ---
#pragma unroll
    for (int off = 16; off > 0; off >>= 1) {
        sumA += __shfl_down_sync(0xFFFFFFFFu, sumA, off);
        sumB += __shfl_down_sync(0xFFFFFFFFu, sumB, off);
    }

    __shared__ float shA[TPB / 32];
    __shared__ float shB[TPB / 32];
    const int lane = threadIdx.x & 31;
    const int wid  = threadIdx.x >> 5;
    if (lane == 0) { shA[wid] = sumA; shB[wid] = sumB; }
    __syncthreads();

    if (wid == 0) {
        sumA = (lane < TPB / 32) ? shA[lane] : 0.0f;
        sumB = (lane < TPB / 32) ? shB[lane] : 0.0f;
#pragma unroll
        for (int off = (TPB / 64); off > 0; off >>= 1) {
            sumA += __shfl_down_sync(0xFFFFFFFFu, sumA, off);
            sumB += __shfl_down_sync(0xFFFFFFFFu, sumB, off);
        }
        if (lane == 0) {
            g_part_err[blockIdx.x] = sumA;
            g_part_nor[blockIdx.x] = sumB;
        }
    }
}

__global__ void __launch_bounds__(256)
reduce_kernel(const float* __restrict__ alpha, float* __restrict__ out,
              int nblocks, int N)
{
    __shared__ double sA[256];
    __shared__ double sB[256];
    double a = 0.0, b = 0.0;
    for (int k = threadIdx.x; k < nblocks; k += 256) {
        a += (double)g_part_err[k];
        b += (double)g_part_nor[k];
    }
    sA[threadIdx.x] = a;
    sB[threadIdx.x] = b;
    __syncthreads();
#pragma unroll
    for (int s = 128; s > 0; s >>= 1) {
        if (threadIdx.x < s) {
            sA[threadIdx.x] += sA[threadIdx.x + s];
            sB[threadIdx.x] += sB[threadIdx.x + s];
        }
        __syncthreads();
    }
    if (threadIdx.x == 0) {
        double invN = 1.0 / (double)N;
        double cost = sA[0] * invN;
        double dive = sB[0] * invN;
        out[0] = (float)(cost + (double)__ldg(alpha) * dive);
    }
}

extern "C" void kernel_launch(void* const* d_in, const int* in_sizes, int n_in,
                              void* d_out, int out_size)
{
    // metadata order: omega, Wh1, bh1, Wh2, bh2, Wr1, br1, Wr2, br2, alpha, n_tasks
    const float* omega = (const float*)d_in[0];
    const float* Wh1   = (const float*)d_in[1];
    const float* bh1   = (const float*)d_in[2];
    const float* Wh2   = (const float*)d_in[3];
    const float* bh2   = (const float*)d_in[4];
    const float* Wr1   = (const float*)d_in[5];
    const float* br1   = (const float*)d_in[6];
    const float* Wr2   = (const float*)d_in[7];
    const float* br2   = (const float*)d_in[8];
    const float* alpha = (const float*)d_in[9];

    const int N = in_sizes[0] / 2;               // omega is [2, N]
    int nblocks = (N + TPB - 1) / TPB;
    if (nblocks > MAX_BLOCKS) nblocks = MAX_BLOCKS;  // safety (N=1M -> 4096)

    rollout_kernel<<<nblocks, TPB>>>(omega, Wh1, bh1, Wh2, bh2,
                                     Wr1, br1, Wr2, br2, N);
    reduce_kernel<<<1, 256>>>(alpha, (float*)d_out, nblocks, N);
}

// round 2
// speedup vs baseline: 1.9903x; 1.9903x over previous
#include <cuda_runtime.h>
#include <cuda_bf16.h>

// 1M independent tasks x 40-step rollout of a tiny control system with two
// small MLPs, reduced to one scalar: mean(err + eff) + alpha * mean(nor).
//
// R2 changes vs R1:
//  - tanh.approx.f32 (1 MUFU op) instead of EX2+RCP (2 MUFU ops)
//  - loop-invariant hoisting: s_star-dependent parts of layer-1 human MLP
//    and the zt target are per-task constants
//  - single fused kernel: last block reduces partials (threadfence+counter),
//    deterministic fixed-order double accumulation, counter self-resets for
//    graph replay.

#define DT      0.05f
#define NSTEPS  40           // N_STEPS - 1 loop iterations
#define TPB     256
#define MAX_BLOCKS 8192

__device__ float g_part_err[MAX_BLOCKS];   // per-block sum of (err + eff)
__device__ float g_part_nor[MAX_BLOCKS];   // per-block sum of nor
__device__ unsigned int g_count = 0;       // arrival counter (self-resetting)

__device__ __forceinline__ float tanh_fast(float x) {
    float y;
    asm("tanh.approx.f32 %0, %1;" : "=f"(y) : "f"(x));
    return y;
}

__global__ void __launch_bounds__(TPB)
rollout_kernel(const float* __restrict__ omega,
               const float* __restrict__ Wh1, const float* __restrict__ bh1,
               const float* __restrict__ Wh2, const float* __restrict__ bh2,
               const float* __restrict__ Wr1, const float* __restrict__ br1,
               const float* __restrict__ Wr2, const float* __restrict__ br2,
               const float* __restrict__ alpha,
               float* __restrict__ out,
               int N, int nblocks)
{
    const int i = blockIdx.x * TPB + threadIdx.x;

    // ---- tiny shared weights -> registers (uniform broadcast loads) ----
    float wh1c2[4], wh1c3[4];          // columns 2,3 of Wh1 (s0,s1 coeffs)
    float wh1c0[4], wh1c1[4], vbh1[4]; // columns 0,1 + bias (hoisted)
    float wh2[4], vbh2;
    float wr1[9], vbr1[3], wr2[3], vbr2;
#pragma unroll
    for (int k = 0; k < 4; k++) {
        wh1c0[k] = __ldg(Wh1 + 4 * k + 0);
        wh1c1[k] = __ldg(Wh1 + 4 * k + 1);
        wh1c2[k] = __ldg(Wh1 + 4 * k + 2);
        wh1c3[k] = __ldg(Wh1 + 4 * k + 3);
        vbh1[k]  = __ldg(bh1 + k);
        wh2[k]   = __ldg(Wh2 + k);
    }
    vbh2 = __ldg(bh2);
#pragma unroll
    for (int k = 0; k < 9; k++) wr1[k] = __ldg(Wr1 + k);
#pragma unroll
    for (int k = 0; k < 3; k++) { vbr1[k] = __ldg(br1 + k); wr2[k] = __ldg(Wr2 + k); }
    vbr2 = __ldg(br2);

    // ---- per-task target ----
    float t0 = 0.0f, t1 = 0.0f;
    if (i < N) {
        t0 = __ldg(omega + i);        // omega[0, i]
        t1 = __ldg(omega + N + i);    // omega[1, i]
    }

    // hoisted per-task constants
    float ch[4];
#pragma unroll
    for (int k = 0; k < 4; k++)
        ch[k] = fmaf(wh1c0[k], t0, fmaf(wh1c1[k], t1, vbh1[k]));
    const float c_zt = fmaf(0.1f, t1, t0);   // zt = c_zt - (s0 + 0.1 s1)

    float s0 = 0.0f, s1 = 0.0f;
    float err = 0.0f, eff = 0.0f, nor = 0.0f;

#pragma unroll 4
    for (int st = 0; st < NSTEPS; st++) {
        float e0 = t0 - s0;
        float e1 = t1 - s1;
        err = fmaf(10.0f * e0, e0, fmaf(e1, e1, err));
        float zt = c_zt - fmaf(0.1f, s1, s0);

        // human MLP (layer-1 s_star part hoisted into ch[])
        float h0 = tanh_fast(fmaf(wh1c2[0], s0, fmaf(wh1c3[0], s1, ch[0])));
        float h1 = tanh_fast(fmaf(wh1c2[1], s0, fmaf(wh1c3[1], s1, ch[1])));
        float h2 = tanh_fast(fmaf(wh1c2[2], s0, fmaf(wh1c3[2], s1, ch[2])));
        float h3 = tanh_fast(fmaf(wh1c2[3], s0, fmaf(wh1c3[3], s1, ch[3])));
        float z  = tanh_fast(fmaf(wh2[0], h0, fmaf(wh2[1], h1,
                             fmaf(wh2[2], h2, fmaf(wh2[3], h3, vbh2)))));

        // robot MLP: xr = [s0, s1, z]
        float r0 = tanh_fast(fmaf(wr1[0], s0, fmaf(wr1[1], s1, fmaf(wr1[2], z, vbr1[0]))));
        float r1 = tanh_fast(fmaf(wr1[3], s0, fmaf(wr1[4], s1, fmaf(wr1[5], z, vbr1[1]))));
        float r2 = tanh_fast(fmaf(wr1[6], s0, fmaf(wr1[7], s1, fmaf(wr1[8], z, vbr1[2]))));
        float a  = fmaf(wr2[0], r0, fmaf(wr2[1], r1, fmaf(wr2[2], r2, vbr2)));

        // dynamics: s = [[1,dt],[0,1]] s + [0,dt] a
        float ns0 = fmaf(DT, s1, s0);
        float ns1 = fmaf(DT, a,  s1);
        s0 = ns0; s1 = ns1;

        eff += (fabsf(z) > 0.01f) ? 1.0f : 0.0f;
        float d = zt - z;
        nor = fmaf(d, d, nor);
    }

    // final error term
    {
        float e0 = t0 - s0;
        float e1 = t1 - s1;
        err = fmaf(10.0f * e0, e0, fmaf(e1, e1, err));
    }

    float sumA = err + eff;
    float sumB = nor;
    if (i >= N) { sumA = 0.0f; sumB = 0.0f; }

    // ---- block reduce (warp shuffles + smem) ----
#pragma unroll
    for (int off = 16; off > 0; off >>= 1) {
        sumA += __shfl_down_sync(0xFFFFFFFFu, sumA, off);
        sumB += __shfl_down_sync(0xFFFFFFFFu, sumB, off);
    }
    __shared__ float shA[TPB / 32];
    __shared__ float shB[TPB / 32];
    const int lane = threadIdx.x & 31;
    const int wid  = threadIdx.x >> 5;
    if (lane == 0) { shA[wid] = sumA; shB[wid] = sumB; }
    __syncthreads();
    if (wid == 0) {
        sumA = (lane < TPB / 32) ? shA[lane] : 0.0f;
        sumB = (lane < TPB / 32) ? shB[lane] : 0.0f;
#pragma unroll
        for (int off = (TPB / 64); off > 0; off >>= 1) {
            sumA += __shfl_down_sync(0xFFFFFFFFu, sumA, off);
            sumB += __shfl_down_sync(0xFFFFFFFFu, sumB, off);
        }
        if (lane == 0) {
            g_part_err[blockIdx.x] = sumA;
            g_part_nor[blockIdx.x] = sumB;
        }
    }

    // ---- last-block final reduction (deterministic order) ----
    __shared__ unsigned int s_is_last;
    __threadfence();
    if (threadIdx.x == 0) {
        unsigned int old = atomicAdd(&g_count, 1u);
        s_is_last = (old == (unsigned int)(nblocks - 1)) ? 1u : 0u;
    }
    __syncthreads();

    if (s_is_last) {
        __shared__ double dA[TPB];
        __shared__ double dB[TPB];
        double a = 0.0, b = 0.0;
        for (int k = threadIdx.x; k < nblocks; k += TPB) {
            a += (double)__ldcg(&g_part_err[k]);   // bypass L1 (other CTAs' data)
            b += (double)__ldcg(&g_part_nor[k]);
        }
        dA[threadIdx.x] = a;
        dB[threadIdx.x] = b;
        __syncthreads();
#pragma unroll
        for (int s = TPB / 2; s > 0; s >>= 1) {
            if (threadIdx.x < s) {
                dA[threadIdx.x] += dA[threadIdx.x + s];
                dB[threadIdx.x] += dB[threadIdx.x + s];
            }
            __syncthreads();
        }
        if (threadIdx.x == 0) {
            double invN = 1.0 / (double)N;
            out[0] = (float)(dA[0] * invN + (double)__ldg(alpha) * (dB[0] * invN));
            g_count = 0;   // self-reset for next graph replay
        }
    }
}

extern "C" void kernel_launch(void* const* d_in, const int* in_sizes, int n_in,
                              void* d_out, int out_size)
{
    // metadata order: omega, Wh1, bh1, Wh2, bh2, Wr1, br1, Wr2, br2, alpha, n_tasks
    const float* omega = (const float*)d_in[0];
    const float* Wh1   = (const float*)d_in[1];
    const float* bh1   = (const float*)d_in[2];
    const float* Wh2   = (const float*)d_in[3];
    const float* bh2   = (const float*)d_in[4];
    const float* Wr1   = (const float*)d_in[5];
    const float* br1   = (const float*)d_in[6];
    const float* Wr2   = (const float*)d_in[7];
    const float* br2   = (const float*)d_in[8];
    const float* alpha = (const float*)d_in[9];

    const int N = in_sizes[0] / 2;                 // omega is [2, N]
    int nblocks = (N + TPB - 1) / TPB;             // N=1M -> 4096
    if (nblocks > MAX_BLOCKS) nblocks = MAX_BLOCKS;

    rollout_kernel<<<nblocks, TPB>>>(omega, Wh1, bh1, Wh2, bh2,
                                     Wr1, br1, Wr2, br2, alpha,
                                     (float*)d_out, N, nblocks);
}